// round 15
// baseline (speedup 1.0000x reference)
#include <cuda_runtime.h>
#include <cstdint>

#define B_     2
#define NRES   2048
#define NATOM  16384
#define CS     384
#define COUT   50
#define OPAD   64
#define KT     64
#define GROWS  8                            // GEMM rows per prologue block
#define PRO_BLOCKS  ((B_ * NRES) / GROWS)   // 512 (all wave-1 resident)
#define NBLOCKS     ((B_ * NATOM) / 8)      // 4096 scan blocks (1 atom/warp)

// Scratch + counters (reset at exit -> graph-replay safe)
__device__ float g_res_logits[B_ * NRES * COUT];   // 3.2 MB (L2-resident)
__device__ int   g_done    = 0;                    // prologue blocks finished
__device__ int   g_blkfin  = 0;                    // blocks fully finished

// ---------------------------------------------------------------------------
// ONE kernel, 4096 blocks:
//   blocks [0,512):  GEMM prologue (8 rows each; all wave-1 resident ->
//                    completes in ~3-5us even under contention), then scan.
//   all blocks:      scan 8 atoms (1/warp, 512-float rounds, MLP=4) ->
//                    per-warp brief spin on g_done -> inline gather -> out.
// No block ever holds a slot waiting on another block's *scan*; the only
// wait target (GEMM prologue) is guaranteed resident and fast.
// ---------------------------------------------------------------------------
__global__ void __launch_bounds__(256, 6)
fused_kernel(const float* __restrict__ s,     // [B, NRES, CS]
             const float* __restrict__ tta,   // [B, NATOM, NRES]
             const float* __restrict__ W,     // [COUT, CS]
             const float* __restrict__ bias,  // [COUT]
             float* __restrict__ out)         // [B, NATOM, COUT]
{
    __shared__ float s_sm[GROWS][KT];   // 2 KB
    __shared__ float wt_sm[KT][OPAD];   // 16 KB (18 KB total)

    const int tid = threadIdx.x;

    // ================= GEMM prologue (blocks 0..511) =================
    if (blockIdx.x < PRO_BLOCKS) {
        const int rows0 = blockIdx.x * GROWS;
        const int o  = tid & 63;            // output channel
        const int rp = tid >> 6;            // row pair 0..3
        const int r0 = rp << 1;
        const int r1 = r0 + 1;

        const int wo = tid & 63;            // W transpose mapping
        const int wg = tid >> 6;

        float acc0 = 0.0f, acc1 = 0.0f;

        for (int kt = 0; kt < CS; kt += KT) {
            // s tile: 8 rows x 64 k = 128 float4; threads 0..127 load one each
            if (tid < 128) {
                const float4* __restrict__ sg = reinterpret_cast<const float4*>(s);
                const int r = tid >> 4;      // 0..7
                const int c = tid & 15;      // 0..15
                *reinterpret_cast<float4*>(&s_sm[r][c << 2]) =
                    sg[(size_t)(rows0 + r) * (CS / 4) + (kt >> 2) + c];
            }
            // W tile transposed: lanes stride o -> conflict-free STS
            #pragma unroll
            for (int m = 0; m < 4; ++m) {
                const int k0 = (wg << 4) + (m << 2);
                float4 v = make_float4(0.f, 0.f, 0.f, 0.f);
                if (wo < COUT)
                    v = *reinterpret_cast<const float4*>(&W[(size_t)wo * CS + kt + k0]);
                wt_sm[k0 + 0][wo] = v.x;
                wt_sm[k0 + 1][wo] = v.y;
                wt_sm[k0 + 2][wo] = v.z;
                wt_sm[k0 + 3][wo] = v.w;
            }
            __syncthreads();

            #pragma unroll 16
            for (int kk = 0; kk < KT; ++kk) {
                const float w  = wt_sm[kk][o];       // stride-1 across lanes
                acc0 = fmaf(s_sm[r0][kk], w, acc0);  // broadcast
                acc1 = fmaf(s_sm[r1][kk], w, acc1);
            }
            __syncthreads();
        }

        if (o < COUT) {
            const float bv = bias[o];
            g_res_logits[(size_t)(rows0 + r0) * COUT + o] = acc0 + bv;
            g_res_logits[(size_t)(rows0 + r1) * COUT + o] = acc1 + bv;
        }

        __threadfence();                 // publish res_logits
        __syncthreads();
        if (tid == 0) atomicAdd(&g_done, 1);
    }

    // ================= scan (all 4096 blocks, 1 atom/warp) =================
    const int gwarp = blockIdx.x * 8 + (tid >> 5);
    const int lane  = tid & 31;

    const float4* __restrict__ row =
        reinterpret_cast<const float4*>(tta + (size_t)gwarp * NRES);

    int idx = 0;
    #pragma unroll 1
    for (int r = 0; r < 4; ++r) {
        float4 v[4];
        #pragma unroll
        for (int j = 0; j < 4; ++j)
            v[j] = __ldcs(&row[r * 128 + j * 32 + lane]);

        int my = -1;
        #pragma unroll
        for (int j = 3; j >= 0; --j) {
            const int jb = (r * 128 + j * 32 + lane) << 2;
            if (v[j].w != 0.0f) my = jb + 3;
            if (v[j].z != 0.0f) my = jb + 2;
            if (v[j].y != 0.0f) my = jb + 1;
            if (v[j].x != 0.0f) my = jb;
        }

        const unsigned m = __ballot_sync(0xffffffffu, my >= 0);
        if (m) {
            idx = __shfl_sync(0xffffffffu, my, __ffs(m) - 1);
            break;
        }
    }

    // ===== brief per-warp wait for the (fast, distributed) GEMM prologue =====
    if (lane == 0) {
        while (*(volatile int*)&g_done < PRO_BLOCKS) __nanosleep(128);
    }
    __syncwarp();
    __threadfence();                     // acquire before reading res_logits

    // ================= inline gather (R6-proven ~free) =================
    const int b = gwarp >> 14;
    const float2* __restrict__ src = reinterpret_cast<const float2*>(
        g_res_logits + ((size_t)b * NRES + idx) * COUT);
    float2* __restrict__ dst = reinterpret_cast<float2*>(
        out + (size_t)gwarp * COUT);
    if (lane < COUT / 2) dst[lane] = src[lane];

    // ================= counter reset (last block) =================
    __syncthreads();
    if (tid == 0) {
        const int old = atomicAdd(&g_blkfin, 1);
        if (old == NBLOCKS - 1) {
            g_done   = 0;
            g_blkfin = 0;
        }
    }
}

extern "C" void kernel_launch(void* const* d_in, const int* in_sizes, int n_in,
                              void* d_out, int out_size)
{
    const float* s    = (const float*)d_in[0];  // [B, NRES, CS]
    const float* tta  = (const float*)d_in[1];  // [B, NATOM, NRES]
    const float* W    = (const float*)d_in[2];  // [COUT, CS]
    const float* bias = (const float*)d_in[3];  // [COUT]
    float* out = (float*)d_out;

    (void)in_sizes; (void)n_in; (void)out_size;

    fused_kernel<<<NBLOCKS, 256>>>(s, tta, W, bias, out);
}

// round 16
// speedup vs baseline: 1.5247x; 1.5247x over previous
#include <cuda_runtime.h>
#include <cstdint>

#define B_     2
#define NRES   2048
#define NATOM  16384
#define CS     384
#define COUT   50
#define OPAD   64
#define KT     64
#define RPB    32
#define GEMM_BLOCKS ((B_ * NRES) / RPB)      // 128
#define HALF_ATOMS  (B_ * NATOM / 2)         // 16384
#define SCAN1_BLOCKS (HALF_ATOMS / 8)        // 2048 (1 atom/warp, 8 warps/blk)
#define GATH_BLOCKS  (HALF_ATOMS / 64)       // 256  (8 atoms/warp, 8 warps/blk)
#define SCAN2_BLOCKS (HALF_ATOMS / 8)        // 2048

// Scratch
__device__ float g_res_logits[B_ * NRES * COUT];   // 3.2 MB (L2-resident)
__device__ int   g_idx[HALF_ATOMS];                // first-half indices, 64 KB

// ---------------------------------------------------------------------------
// K1: blocks [0,128)      GEMM res_logits = s @ W^T + b (hidden under scan)
//     blocks [128,2176)   scan atoms [0, 16384) -> g_idx  (1 atom/warp, MLP=4)
// ---------------------------------------------------------------------------
__global__ void __launch_bounds__(256)
k1_gemm_scan(const float* __restrict__ s,     // [B, NRES, CS]
             const float* __restrict__ tta,   // [B, NATOM, NRES]
             const float* __restrict__ W,     // [COUT, CS]
             const float* __restrict__ bias)  // [COUT]
{
    __shared__ float s_sm[RPB][KT];     // 8 KB
    __shared__ float wt_sm[KT][OPAD];   // 16 KB

    const int tid = threadIdx.x;

    if (blockIdx.x < GEMM_BLOCKS) {
        // ----------------- GEMM branch (R9-exact) -----------------
        const int to  = tid & 15;
        const int tr  = tid >> 4;
        const int o0  = to << 2;
        const int r0  = tr << 1;
        const int r1  = r0 + 1;
        const int row0 = blockIdx.x * RPB;

        const int wo = tid & 63;
        const int wg = tid >> 6;

        float4 accA = make_float4(0.f, 0.f, 0.f, 0.f);
        float4 accB = make_float4(0.f, 0.f, 0.f, 0.f);

        for (int kt = 0; kt < CS; kt += KT) {
            {
                const float4* __restrict__ sg = reinterpret_cast<const float4*>(s);
                float4* s4 = reinterpret_cast<float4*>(&s_sm[0][0]);
                #pragma unroll
                for (int i = 0; i < 2; ++i) {
                    const int f = tid + 256 * i;
                    const int r = f >> 4;
                    const int c = f & 15;
                    s4[f] = sg[(size_t)(row0 + r) * (CS / 4) + (kt >> 2) + c];
                }
            }
            #pragma unroll
            for (int m = 0; m < 4; ++m) {
                const int k0 = (wg << 4) + (m << 2);
                float4 v = make_float4(0.f, 0.f, 0.f, 0.f);
                if (wo < COUT)
                    v = *reinterpret_cast<const float4*>(&W[(size_t)wo * CS + kt + k0]);
                wt_sm[k0 + 0][wo] = v.x;
                wt_sm[k0 + 1][wo] = v.y;
                wt_sm[k0 + 2][wo] = v.z;
                wt_sm[k0 + 3][wo] = v.w;
            }
            __syncthreads();

            #pragma unroll
            for (int kk = 0; kk < KT; kk += 4) {
                const float4 sa = *reinterpret_cast<const float4*>(&s_sm[r0][kk]);
                const float4 sb = *reinterpret_cast<const float4*>(&s_sm[r1][kk]);
                const float4 w0 = *reinterpret_cast<const float4*>(&wt_sm[kk + 0][o0]);
                const float4 w1 = *reinterpret_cast<const float4*>(&wt_sm[kk + 1][o0]);
                const float4 w2 = *reinterpret_cast<const float4*>(&wt_sm[kk + 2][o0]);
                const float4 w3 = *reinterpret_cast<const float4*>(&wt_sm[kk + 3][o0]);

                accA.x = fmaf(sa.x, w0.x, accA.x); accA.y = fmaf(sa.x, w0.y, accA.y);
                accA.z = fmaf(sa.x, w0.z, accA.z); accA.w = fmaf(sa.x, w0.w, accA.w);
                accB.x = fmaf(sb.x, w0.x, accB.x); accB.y = fmaf(sb.x, w0.y, accB.y);
                accB.z = fmaf(sb.x, w0.z, accB.z); accB.w = fmaf(sb.x, w0.w, accB.w);

                accA.x = fmaf(sa.y, w1.x, accA.x); accA.y = fmaf(sa.y, w1.y, accA.y);
                accA.z = fmaf(sa.y, w1.z, accA.z); accA.w = fmaf(sa.y, w1.w, accA.w);
                accB.x = fmaf(sb.y, w1.x, accB.x); accB.y = fmaf(sb.y, w1.y, accB.y);
                accB.z = fmaf(sb.y, w1.z, accB.z); accB.w = fmaf(sb.y, w1.w, accB.w);

                accA.x = fmaf(sa.z, w2.x, accA.x); accA.y = fmaf(sa.z, w2.y, accA.y);
                accA.z = fmaf(sa.z, w2.z, accA.z); accA.w = fmaf(sa.z, w2.w, accA.w);
                accB.x = fmaf(sb.z, w2.x, accB.x); accB.y = fmaf(sb.z, w2.y, accB.y);
                accB.z = fmaf(sb.z, w2.z, accB.z); accB.w = fmaf(sb.z, w2.w, accB.w);

                accA.x = fmaf(sa.w, w3.x, accA.x); accA.y = fmaf(sa.w, w3.y, accA.y);
                accA.z = fmaf(sa.w, w3.z, accA.z); accA.w = fmaf(sa.w, w3.w, accA.w);
                accB.x = fmaf(sb.w, w3.x, accB.x); accB.y = fmaf(sb.w, w3.y, accB.y);
                accB.z = fmaf(sb.w, w3.z, accB.z); accB.w = fmaf(sb.w, w3.w, accB.w);
            }
            __syncthreads();
        }

        const float aA[4] = {accA.x, accA.y, accA.z, accA.w};
        const float aB[4] = {accB.x, accB.y, accB.z, accB.w};
        #pragma unroll
        for (int c = 0; c < 4; ++c) {
            const int o = o0 + c;
            if (o < COUT) {
                const float bv = bias[o];
                g_res_logits[(size_t)(row0 + r0) * COUT + o] = aA[c] + bv;
                g_res_logits[(size_t)(row0 + r1) * COUT + o] = aB[c] + bv;
            }
        }
    } else {
        // -------- scan atoms [0, 16384): 1 atom/warp, MLP=4 --------
        const int gwarp = (blockIdx.x - GEMM_BLOCKS) * 8 + (tid >> 5);
        const int lane  = tid & 31;

        const float4* __restrict__ row =
            reinterpret_cast<const float4*>(tta + (size_t)gwarp * NRES);

        int idx = 0;
        #pragma unroll 1
        for (int r = 0; r < 4; ++r) {
            float4 v[4];
            #pragma unroll
            for (int j = 0; j < 4; ++j)
                v[j] = __ldcs(&row[r * 128 + j * 32 + lane]);

            int my = -1;
            #pragma unroll
            for (int j = 3; j >= 0; --j) {
                const int jb = (r * 128 + j * 32 + lane) << 2;
                if (v[j].w != 0.0f) my = jb + 3;
                if (v[j].z != 0.0f) my = jb + 2;
                if (v[j].y != 0.0f) my = jb + 1;
                if (v[j].x != 0.0f) my = jb;
            }

            const unsigned m = __ballot_sync(0xffffffffu, my >= 0);
            if (m) {
                idx = __shfl_sync(0xffffffffu, my, __ffs(m) - 1);
                break;
            }
        }

        if (lane == 0) g_idx[gwarp] = idx;
    }
}

// ---------------------------------------------------------------------------
// K2: blocks [0,256)      gather first-half atoms (8 atoms/warp) from g_idx +
//                         res_logits (both complete from K1; hidden under scan)
//     blocks [256,2304)   scan atoms [16384, 32768) with INLINE gather
//                         (res_logits complete from K1)
// ---------------------------------------------------------------------------
__global__ void __launch_bounds__(256)
k2_gather_scan(const float* __restrict__ tta,   // [B, NATOM, NRES]
               float* __restrict__ out)         // [B, NATOM, COUT]
{
    const int tid  = threadIdx.x;
    const int lane = tid & 31;

    if (blockIdx.x < GATH_BLOCKS) {
        // -------- gather branch: 8 atoms/warp, first-half atoms (b=0..) -----
        const int gw = blockIdx.x * 8 + (tid >> 5);   // 0..2047
        const int a0 = gw * 8;                        // 0..16376

        int myv = 0;
        if (lane < 8) myv = g_idx[a0 + lane];

        const int b = a0 >> 14;                       // uniform for the 8
        const float* __restrict__ base = g_res_logits + (size_t)b * NRES * COUT;

        const float2* src[8];
        #pragma unroll
        for (int j = 0; j < 8; ++j) {
            const int ij = __shfl_sync(0xffffffffu, myv, j);
            src[j] = reinterpret_cast<const float2*>(base + (size_t)ij * COUT);
        }

        if (lane < COUT / 2) {
            float2 x[8];
            #pragma unroll
            for (int j = 0; j < 8; ++j)
                x[j] = src[j][lane];
            float2* __restrict__ d =
                reinterpret_cast<float2*>(out + (size_t)a0 * COUT);
            #pragma unroll
            for (int j = 0; j < 8; ++j)
                d[lane + 25 * j] = x[j];              // 25 float2 per atom
        }
    } else {
        // -------- scan atoms [16384, 32768) + inline gather --------
        const int gwarp = HALF_ATOMS +
                          (blockIdx.x - GATH_BLOCKS) * 8 + (tid >> 5);

        const float4* __restrict__ row =
            reinterpret_cast<const float4*>(tta + (size_t)gwarp * NRES);

        int idx = 0;
        #pragma unroll 1
        for (int r = 0; r < 4; ++r) {
            float4 v[4];
            #pragma unroll
            for (int j = 0; j < 4; ++j)
                v[j] = __ldcs(&row[r * 128 + j * 32 + lane]);

            int my = -1;
            #pragma unroll
            for (int j = 3; j >= 0; --j) {
                const int jb = (r * 128 + j * 32 + lane) << 2;
                if (v[j].w != 0.0f) my = jb + 3;
                if (v[j].z != 0.0f) my = jb + 2;
                if (v[j].y != 0.0f) my = jb + 1;
                if (v[j].x != 0.0f) my = jb;
            }

            const unsigned m = __ballot_sync(0xffffffffu, my >= 0);
            if (m) {
                idx = __shfl_sync(0xffffffffu, my, __ffs(m) - 1);
                break;
            }
        }

        // inline gather (R6-proven ~free): 25 lanes x float2
        const int b = gwarp >> 14;
        const float2* __restrict__ src = reinterpret_cast<const float2*>(
            g_res_logits + ((size_t)b * NRES + idx) * COUT);
        float2* __restrict__ dst = reinterpret_cast<float2*>(
            out + (size_t)gwarp * COUT);
        if (lane < COUT / 2) dst[lane] = src[lane];
    }
}

extern "C" void kernel_launch(void* const* d_in, const int* in_sizes, int n_in,
                              void* d_out, int out_size)
{
    const float* s    = (const float*)d_in[0];  // [B, NRES, CS]
    const float* tta  = (const float*)d_in[1];  // [B, NATOM, NRES]
    const float* W    = (const float*)d_in[2];  // [COUT, CS]
    const float* bias = (const float*)d_in[3];  // [COUT]
    float* out = (float*)d_out;

    (void)in_sizes; (void)n_in; (void)out_size;

    k1_gemm_scan<<<GEMM_BLOCKS + SCAN1_BLOCKS, 256>>>(s, tta, W, bias);
    k2_gather_scan<<<GATH_BLOCKS + SCAN2_BLOCKS, 256>>>(tta, out);
}